// round 11
// baseline (speedup 1.0000x reference)
#include <cuda_runtime.h>

#define SEQ   1024
#define BATCH 512
#define NT    64
#define TPB   32    // ONE warp per chain half; lane owns tags {lane, lane+32}

// Scratch (device globals; no allocation).
__device__ float g_vec[2][BATCH][NT];  // [0]=forward F~, [1]=backward u
__device__ int   g_kt[2][BATCH];
__device__ float g_num[BATCH];
__device__ int   g_pair[BATCH];
__device__ float g_llh[BATCH];
__device__ int   g_done;

typedef unsigned long long u64;

__device__ __forceinline__ u64 fma2(u64 a, u64 b, u64 c) {
    u64 d;
    asm("fma.rn.f32x2 %0, %1, %2, %3;" : "=l"(d) : "l"(a), "l"(b), "l"(c));
    return d;
}
__device__ __forceinline__ u64 add2(u64 a, u64 b) {
    u64 d;
    asm("add.rn.f32x2 %0, %1, %2;" : "=l"(d) : "l"(a), "l"(b));
    return d;
}
__device__ __forceinline__ u64 pack2(float lo, float hi) {
    u64 r;
    asm("mov.b64 %0, {%1,%2};" : "=l"(r) : "f"(lo), "f"(hi));
    return r;
}
__device__ __forceinline__ void unpack2(u64 v, float& lo, float& hi) {
    asm("mov.b64 {%0,%1}, %2;" : "=f"(lo), "=f"(hi) : "l"(v));
}

__global__ void __launch_bounds__(TPB, 1)
crf_kernel(const float* __restrict__ em,
           const void* __restrict__ tags_raw,
           const int* __restrict__ mask,
           const float* __restrict__ startT,
           const float* __restrict__ endT,
           const float* __restrict__ trans,
           float* __restrict__ out)
{
    const int bb   = blockIdx.x;
    const int b    = bb >> 1;         // batch
    const int half = bb & 1;          // 0 = forward, 1 = backward
    const int lane = threadIdx.x;     // 0..31
    const int jlo  = lane;            // first owned tag
    const int jhi  = lane + 32;       // second owned tag

    // duplicated beta, double-buffered: shdup[buf][2i] = shdup[buf][2i+1] = beta_i
    __shared__ __align__(16) float shdup[2][2 * NT];

    // ---- exp(transitions), f32x2 packed over the TWO OWNED TAGS ----
    // forward : coeff for tag j at row i = exp(trans[i][j])
    // backward: coeff for tag j at row i = exp(trans[j][i])
    u64 eT2[NT];
    if (half == 0) {
#pragma unroll
        for (int i = 0; i < NT; ++i)
            eT2[i] = pack2(__expf(trans[i * NT + jlo]),
                           __expf(trans[i * NT + jhi]));
    } else {
#pragma unroll
        for (int i = 0; i < NT; ++i)
            eT2[i] = pack2(__expf(trans[jlo * NT + i]),
                           __expf(trans[jhi * NT + i]));
    }

    // ---- sequence length (mask monotone: mask[t] = t < length) ----
    int cnt = 0;
    for (int t = lane; t < SEQ; t += 32)
        cnt += mask[t * BATCH + b];
#pragma unroll
    for (int o = 16; o > 0; o >>= 1)
        cnt += __shfl_xor_sync(0xffffffffu, cnt, o);
    const int length = cnt;

    const int m = (length - 1) >> 1;           // meeting point
    const int n = half ? (length - 1 - m) : m; // my step count

    // ---- numerator (forward block only) ----
    if (half == 0) {
        const int*       t32 = (const int*)tags_raw;
        const long long* t64 = (const long long*)tags_raw;
        bool is64 = true;
#pragma unroll
        for (int k = 0; k < 16; ++k)
            is64 = is64 && (t32[2 * k * 1031 + 1] == 0);

        float num = 0.f;
        if (is64) {
            for (int t = 1 + lane; t < length; t += 32) {
                const int pt = (int)t64[(t - 1) * BATCH + b];
                const int ct = (int)t64[t * BATCH + b];
                num += trans[pt * NT + ct] + em[(t * BATCH + b) * NT + ct];
            }
        } else {
            for (int t = 1 + lane; t < length; t += 32) {
                const int pt = t32[(t - 1) * BATCH + b];
                const int ct = t32[t * BATCH + b];
                num += trans[pt * NT + ct] + em[(t * BATCH + b) * NT + ct];
            }
        }
#pragma unroll
        for (int o = 16; o > 0; o >>= 1)
            num += __shfl_xor_sync(0xffffffffu, num, o);
        if (lane == 0) {
            const int t0 = is64 ? (int)t64[b] : t32[b];
            const int tl = is64 ? (int)t64[(length - 1) * BATCH + b]
                                : t32[(length - 1) * BATCH + b];
            g_num[b] = num + startT[t0] + em[b * NT + t0] + endT[tl];
        }
    }

    // ---- em index mapping ----
    // forward : step v uses em[v];       init = exp(start + em_0)
    // backward: step v uses em[L-1-v];   init = exp(end + em_{L-1})
    const int row0   = half ? (length - 1) : 0;
    const int stride = half ? -(BATCH * NT) : (BATCH * NT);
    const int base_lo = (row0 * BATCH + b) * NT + jlo;
    const int base_hi = (row0 * BATCH + b) * NT + jhi;

    {
        const float b_lo = half ? __expf(endT[jlo] + em[base_lo])
                                : __expf(startT[jlo] + em[base_lo]);
        const float b_hi = half ? __expf(endT[jhi] + em[base_hi])
                                : __expf(startT[jhi] + em[base_hi]);
        ((u64*)shdup[0])[jlo] = pack2(b_lo, b_lo);
        ((u64*)shdup[0])[jhi] = pack2(b_hi, b_hi);
    }

    // register prefetch for steps v..v+3 (both tag streams)
    float plo0 = (1 <= n) ? em[base_lo + 1 * stride] : 0.f;
    float plo1 = (2 <= n) ? em[base_lo + 2 * stride] : 0.f;
    float plo2 = (3 <= n) ? em[base_lo + 3 * stride] : 0.f;
    float plo3 = (4 <= n) ? em[base_lo + 4 * stride] : 0.f;
    float phi0 = (1 <= n) ? em[base_hi + 1 * stride] : 0.f;
    float phi1 = (2 <= n) ? em[base_hi + 2 * stride] : 0.f;
    float phi2 = (3 <= n) ? em[base_hi + 3 * stride] : 0.f;
    float phi3 = (4 <= n) ? em[base_hi + 4 * stride] : 0.f;

    int ktot = 0;
    __syncwarp();

#define STEP(PP, EXLO, EXHI, RENORM) do {                                   \
        const ulonglong2* __restrict__ e2 = (const ulonglong2*)shdup[PP];    \
        float scale_ = 1.0f;                                                 \
        if (RENORM) {                                                        \
            const int kk =                                                   \
                ((__float_as_int(shdup[PP][0]) >> 23) & 0xFF) - 127;         \
            scale_ = __int_as_float((127 - kk) << 23);                       \
            ktot += kk;                                                      \
        }                                                                    \
        u64 a0 = 0ull, a1 = 0ull, a2 = 0ull, a3 = 0ull;                      \
        _Pragma("unroll")                                                    \
        for (int k = 0; k < 32; ++k) {       /* rows 2k, 2k+1 */             \
            const ulonglong2 q = e2[k];      /* (b_2k,b_2k),(b_2k+1,..) */   \
            if (k & 1) { a2 = fma2(q.x, eT2[2 * k],     a2);                 \
                         a3 = fma2(q.y, eT2[2 * k + 1], a3); }               \
            else       { a0 = fma2(q.x, eT2[2 * k],     a0);                 \
                         a1 = fma2(q.y, eT2[2 * k + 1], a1); }               \
        }                                                                    \
        const u64 d_ = add2(add2(a0, a1), add2(a2, a3));                     \
        float dlo_, dhi_;                                                    \
        unpack2(d_, dlo_, dhi_);                                             \
        const float blo_ = dlo_ * ((EXLO) * scale_);                         \
        const float bhi_ = dhi_ * ((EXHI) * scale_);                         \
        ((u64*)shdup[(PP) ^ 1])[jlo] = pack2(blo_, blo_);                    \
        ((u64*)shdup[(PP) ^ 1])[jhi] = pack2(bhi_, bhi_);                    \
        __syncwarp();                                                        \
    } while (0)

    int v = 1;
    for (; v + 3 <= n; v += 4) {
        const float nlo0 = (v + 4 <= n) ? em[base_lo + (v + 4) * stride] : 0.f;
        const float nlo1 = (v + 5 <= n) ? em[base_lo + (v + 5) * stride] : 0.f;
        const float nlo2 = (v + 6 <= n) ? em[base_lo + (v + 6) * stride] : 0.f;
        const float nlo3 = (v + 7 <= n) ? em[base_lo + (v + 7) * stride] : 0.f;
        const float nhi0 = (v + 4 <= n) ? em[base_hi + (v + 4) * stride] : 0.f;
        const float nhi1 = (v + 5 <= n) ? em[base_hi + (v + 5) * stride] : 0.f;
        const float nhi2 = (v + 6 <= n) ? em[base_hi + (v + 6) * stride] : 0.f;
        const float nhi3 = (v + 7 <= n) ? em[base_hi + (v + 7) * stride] : 0.f;

        const float exlo0 = __expf(plo0), exhi0 = __expf(phi0);
        const float exlo1 = __expf(plo1), exhi1 = __expf(phi1);
        const float exlo2 = __expf(plo2), exhi2 = __expf(phi2);
        const float exlo3 = __expf(plo3), exhi3 = __expf(phi3);

        STEP(0, exlo0, exhi0, true);
        STEP(1, exlo1, exhi1, false);
        STEP(0, exlo2, exhi2, false);
        STEP(1, exlo3, exhi3, false);

        plo0 = nlo0; plo1 = nlo1; plo2 = nlo2; plo3 = nlo3;
        phi0 = nhi0; phi1 = nhi1; phi2 = nhi2; phi3 = nhi3;
    }
    if (v     <= n) STEP(0, __expf(plo0), __expf(phi0), false);
    if (v + 1 <= n) STEP(1, __expf(plo1), __expf(phi1), false);
    if (v + 2 <= n) STEP(0, __expf(plo2), __expf(phi2), false);
#undef STEP

    // ---- publish my half (de-duplicated values) ----
    g_vec[half][b][jlo] = shdup[n & 1][2 * jlo];
    g_vec[half][b][jhi] = shdup[n & 1][2 * jhi];
    if (lane == 0) g_kt[half][b] = ktot;

    __threadfence();
    int go = 0;
    if (lane == 0)
        go = (atomicAdd(&g_pair[b], 1) == 1) ? 1 : 0;
    go = __shfl_sync(0xffffffffu, go, 0);

    if (go) {
        __threadfence();   // acquire side
        // Z = sum_j F_m(j) * u_m(j) * exp(-em_m(j))
        const int eb = (m * BATCH + b) * NT;
        float s = g_vec[0][b][jlo] * g_vec[1][b][jlo] * __expf(-em[eb + jlo])
                + g_vec[0][b][jhi] * g_vec[1][b][jhi] * __expf(-em[eb + jhi]);
#pragma unroll
        for (int o = 16; o > 0; o >>= 1)
            s += __shfl_xor_sync(0xffffffffu, s, o);

        if (lane == 0) {
            const int kt = g_kt[0][b] + g_kt[1][b];
            const double denom = (double)kt * 0.6931471805599453
                               + (double)logf(s);
            g_llh[b] = (float)((double)g_num[b] - denom);
            g_pair[b] = 0;                 // reset for next replay
        }

        // ---- final reduction by the last combiner ----
        __threadfence();
        int last = 0;
        if (lane == 0)
            last = (atomicAdd(&g_done, 1) == BATCH - 1) ? 1 : 0;
        last = __shfl_sync(0xffffffffu, last, 0);

        if (last) {
            double acc = 0.0;
#pragma unroll
            for (int k = 0; k < BATCH / 32; ++k)       // fixed order: 16 each
                acc += (double)g_llh[lane + k * 32];
#pragma unroll
            for (int o = 16; o > 0; o >>= 1)
                acc += __shfl_xor_sync(0xffffffffu, acc, o);
            if (lane == 0) {
                out[0] = (float)acc;
                atomicExch(&g_done, 0);    // reset for next replay
            }
        }
    }
}

extern "C" void kernel_launch(void* const* d_in, const int* in_sizes, int n_in,
                              void* d_out, int out_size)
{
    const float* em     = (const float*)d_in[0];
    const void*  tags   = (const void*)d_in[1];
    const int*   mask   = (const int*)d_in[2];
    const float* startT = (const float*)d_in[3];
    const float* endT   = (const float*)d_in[4];
    const float* trans  = (const float*)d_in[5];
    float* out = (float*)d_out;

    crf_kernel<<<2 * BATCH, TPB>>>(em, tags, mask, startT, endT, trans, out);
}

// round 12
// speedup vs baseline: 1.3458x; 1.3458x over previous
#include <cuda_runtime.h>
#include <cuda_bf16.h>

#define SEQ   1024
#define BATCH 512
#define NT    64
#define TPB   32    // ONE warp per chain half; lane owns tags {2L, 2L+1}

// Scratch (device globals; no allocation).
__device__ float g_vec[2][BATCH][NT];  // [0]=forward F~, [1]=backward u
__device__ int   g_kt[2][BATCH];
__device__ float g_num[BATCH];
__device__ int   g_pair[BATCH];
__device__ float g_llh[BATCH];
__device__ int   g_done;

__global__ void __launch_bounds__(TPB, 1)
crf_kernel(const float* __restrict__ em,
           const void* __restrict__ tags_raw,
           const int* __restrict__ mask,
           const float* __restrict__ startT,
           const float* __restrict__ endT,
           const float* __restrict__ trans,
           float* __restrict__ out)
{
    const int bb   = blockIdx.x;
    const int b    = bb >> 1;         // batch
    const int half = bb & 1;          // 0 = forward, 1 = backward
    const int lane = threadIdx.x;     // 0..31
    const int j0   = 2 * lane;        // owned tags (adjacent)
    const int j1   = 2 * lane + 1;

    // beta in bf16 pairs, double-buffered: shB[buf][p] = (beta_2p, beta_2p+1)
    __shared__ __align__(16) __nv_bfloat162 shB[2][NT / 2];

    // ---- exp(transitions) in bf16x2, packed over ROW PAIRS (2k, 2k+1) ----
    // forward : coeff for tag j at row i = exp(trans[i][j])
    // backward: coeff for tag j at row i = exp(trans[j][i])
    __nv_bfloat162 hT0[NT / 2], hT1[NT / 2];
    if (half == 0) {
#pragma unroll
        for (int k = 0; k < NT / 2; ++k) {
            hT0[k] = __floats2bfloat162_rn(__expf(trans[(2 * k) * NT + j0]),
                                           __expf(trans[(2 * k + 1) * NT + j0]));
            hT1[k] = __floats2bfloat162_rn(__expf(trans[(2 * k) * NT + j1]),
                                           __expf(trans[(2 * k + 1) * NT + j1]));
        }
    } else {
#pragma unroll
        for (int k = 0; k < NT / 2; ++k) {
            hT0[k] = __floats2bfloat162_rn(__expf(trans[j0 * NT + 2 * k]),
                                           __expf(trans[j0 * NT + 2 * k + 1]));
            hT1[k] = __floats2bfloat162_rn(__expf(trans[j1 * NT + 2 * k]),
                                           __expf(trans[j1 * NT + 2 * k + 1]));
        }
    }

    // ---- sequence length (mask monotone: mask[t] = t < length) ----
    int cnt = 0;
    for (int t = lane; t < SEQ; t += 32)
        cnt += mask[t * BATCH + b];
#pragma unroll
    for (int o = 16; o > 0; o >>= 1)
        cnt += __shfl_xor_sync(0xffffffffu, cnt, o);
    const int length = cnt;

    const int m = (length - 1) >> 1;           // meeting point
    const int n = half ? (length - 1 - m) : m; // my step count

    // ---- numerator (forward block only) ----
    if (half == 0) {
        const int*       t32 = (const int*)tags_raw;
        const long long* t64 = (const long long*)tags_raw;
        bool is64 = true;
#pragma unroll
        for (int k = 0; k < 16; ++k)
            is64 = is64 && (t32[2 * k * 1031 + 1] == 0);

        float num = 0.f;
        if (is64) {
            for (int t = 1 + lane; t < length; t += 32) {
                const int pt = (int)t64[(t - 1) * BATCH + b];
                const int ct = (int)t64[t * BATCH + b];
                num += trans[pt * NT + ct] + em[(t * BATCH + b) * NT + ct];
            }
        } else {
            for (int t = 1 + lane; t < length; t += 32) {
                const int pt = t32[(t - 1) * BATCH + b];
                const int ct = t32[t * BATCH + b];
                num += trans[pt * NT + ct] + em[(t * BATCH + b) * NT + ct];
            }
        }
#pragma unroll
        for (int o = 16; o > 0; o >>= 1)
            num += __shfl_xor_sync(0xffffffffu, num, o);
        if (lane == 0) {
            const int t0 = is64 ? (int)t64[b] : t32[b];
            const int tl = is64 ? (int)t64[(length - 1) * BATCH + b]
                                : t32[(length - 1) * BATCH + b];
            g_num[b] = num + startT[t0] + em[b * NT + t0] + endT[tl];
        }
    }

    // ---- em index mapping: owned tags are adjacent -> float2 loads ----
    // forward : step v uses em[v];       init = exp(start + em_0)
    // backward: step v uses em[L-1-v];   init = exp(end + em_{L-1})
    const int row0    = half ? (length - 1) : 0;
    const int strideV = half ? -(BATCH * NT / 2) : (BATCH * NT / 2); // float2 units
    const float2* __restrict__ em2 = (const float2*)em;
    const int base2 = (row0 * BATCH + b) * (NT / 2) + lane;

    {
        const float2 e0 = em2[base2];
        const float b0 = half ? __expf(endT[j0] + e0.x) : __expf(startT[j0] + e0.x);
        const float b1 = half ? __expf(endT[j1] + e0.y) : __expf(startT[j1] + e0.y);
        shB[0][lane] = __floats2bfloat162_rn(b0, b1);
    }

    // register prefetch of raw em float2 for steps v..v+3
    float2 p0 = (1 <= n) ? em2[base2 + 1 * strideV] : make_float2(0.f, 0.f);
    float2 p1 = (2 <= n) ? em2[base2 + 2 * strideV] : make_float2(0.f, 0.f);
    float2 p2 = (3 <= n) ? em2[base2 + 3 * strideV] : make_float2(0.f, 0.f);
    float2 p3 = (4 <= n) ? em2[base2 + 4 * strideV] : make_float2(0.f, 0.f);

    int ktot = 0;
    __syncwarp();

    const __nv_bfloat162 hz = __floats2bfloat162_rn(0.f, 0.f);

#define STEP(PP, EXLO, EXHI, RENORM) do {                                    \
        const uint4* __restrict__ e4 = (const uint4*)shB[PP];                 \
        float scale_ = 1.0f;                                                  \
        if (RENORM) {                                                         \
            const unsigned w0 = *(const unsigned*)&shB[PP][0];                \
            const int kk = (int)((w0 >> 7) & 0xFFu) - 127;                    \
            scale_ = __int_as_float((127 - kk) << 23);                        \
            ktot += kk;                                                       \
        }                                                                     \
        __nv_bfloat162 a00 = hz, a01 = hz, a02 = hz, a03 = hz;                \
        __nv_bfloat162 a10 = hz, a11 = hz, a12 = hz, a13 = hz;                \
        _Pragma("unroll")                                                     \
        for (int k = 0; k < 8; ++k) {          /* rows 8k .. 8k+7 */          \
            const uint4 q = e4[k];                                            \
            const __nv_bfloat162 q0 = *(const __nv_bfloat162*)&q.x;           \
            const __nv_bfloat162 q1 = *(const __nv_bfloat162*)&q.y;           \
            const __nv_bfloat162 q2 = *(const __nv_bfloat162*)&q.z;           \
            const __nv_bfloat162 q3 = *(const __nv_bfloat162*)&q.w;           \
            a00 = __hfma2(q0, hT0[4 * k + 0], a00);                           \
            a10 = __hfma2(q0, hT1[4 * k + 0], a10);                           \
            a01 = __hfma2(q1, hT0[4 * k + 1], a01);                           \
            a11 = __hfma2(q1, hT1[4 * k + 1], a11);                           \
            a02 = __hfma2(q2, hT0[4 * k + 2], a02);                           \
            a12 = __hfma2(q2, hT1[4 * k + 2], a12);                           \
            a03 = __hfma2(q3, hT0[4 * k + 3], a03);                           \
            a13 = __hfma2(q3, hT1[4 * k + 3], a13);                           \
        }                                                                     \
        const __nv_bfloat162 s0 =                                             \
            __hadd2(__hadd2(a00, a01), __hadd2(a02, a03));                    \
        const __nv_bfloat162 s1 =                                             \
            __hadd2(__hadd2(a10, a11), __hadd2(a12, a13));                    \
        const float2 f0 = __bfloat1622float2(s0);                             \
        const float2 f1 = __bfloat1622float2(s1);                             \
        const float b0_ = (f0.x + f0.y) * ((EXLO) * scale_);                  \
        const float b1_ = (f1.x + f1.y) * ((EXHI) * scale_);                  \
        shB[(PP) ^ 1][lane] = __floats2bfloat162_rn(b0_, b1_);                \
        __syncwarp();                                                         \
    } while (0)

    int v = 1;
    for (; v + 3 <= n; v += 4) {
        const float2 q0 = (v + 4 <= n) ? em2[base2 + (v + 4) * strideV] : make_float2(0.f, 0.f);
        const float2 q1 = (v + 5 <= n) ? em2[base2 + (v + 5) * strideV] : make_float2(0.f, 0.f);
        const float2 q2 = (v + 6 <= n) ? em2[base2 + (v + 6) * strideV] : make_float2(0.f, 0.f);
        const float2 q3 = (v + 7 <= n) ? em2[base2 + (v + 7) * strideV] : make_float2(0.f, 0.f);

        const float ex0l = __expf(p0.x), ex0h = __expf(p0.y);
        const float ex1l = __expf(p1.x), ex1h = __expf(p1.y);
        const float ex2l = __expf(p2.x), ex2h = __expf(p2.y);
        const float ex3l = __expf(p3.x), ex3h = __expf(p3.y);

        STEP(0, ex0l, ex0h, true);
        STEP(1, ex1l, ex1h, false);
        STEP(0, ex2l, ex2h, false);
        STEP(1, ex3l, ex3h, false);

        p0 = q0; p1 = q1; p2 = q2; p3 = q3;
    }
    if (v     <= n) STEP(0, __expf(p0.x), __expf(p0.y), false);
    if (v + 1 <= n) STEP(1, __expf(p1.x), __expf(p1.y), false);
    if (v + 2 <= n) STEP(0, __expf(p2.x), __expf(p2.y), false);
#undef STEP

    // ---- publish my half (fp32) ----
    {
        const float2 f = __bfloat1622float2(shB[n & 1][lane]);
        g_vec[half][b][j0] = f.x;
        g_vec[half][b][j1] = f.y;
        if (lane == 0) g_kt[half][b] = ktot;
    }

    __threadfence();
    int go = 0;
    if (lane == 0)
        go = (atomicAdd(&g_pair[b], 1) == 1) ? 1 : 0;
    go = __shfl_sync(0xffffffffu, go, 0);

    if (go) {
        __threadfence();   // acquire side
        // Z = sum_j F_m(j) * u_m(j) * exp(-em_m(j))
        const int eb = (m * BATCH + b) * NT;
        const int ja = lane, jb = lane + 32;
        float s = g_vec[0][b][ja] * g_vec[1][b][ja] * __expf(-em[eb + ja])
                + g_vec[0][b][jb] * g_vec[1][b][jb] * __expf(-em[eb + jb]);
#pragma unroll
        for (int o = 16; o > 0; o >>= 1)
            s += __shfl_xor_sync(0xffffffffu, s, o);

        if (lane == 0) {
            const int kt = g_kt[0][b] + g_kt[1][b];
            const double denom = (double)kt * 0.6931471805599453
                               + (double)logf(s);
            g_llh[b] = (float)((double)g_num[b] - denom);
            g_pair[b] = 0;                 // reset for next replay
        }

        // ---- final reduction by the last combiner ----
        __threadfence();
        int last = 0;
        if (lane == 0)
            last = (atomicAdd(&g_done, 1) == BATCH - 1) ? 1 : 0;
        last = __shfl_sync(0xffffffffu, last, 0);

        if (last) {
            double acc = 0.0;
#pragma unroll
            for (int k = 0; k < BATCH / 32; ++k)       // fixed order: 16 each
                acc += (double)g_llh[lane + k * 32];
#pragma unroll
            for (int o = 16; o > 0; o >>= 1)
                acc += __shfl_xor_sync(0xffffffffu, acc, o);
            if (lane == 0) {
                out[0] = (float)acc;
                atomicExch(&g_done, 0);    // reset for next replay
            }
        }
    }
}

extern "C" void kernel_launch(void* const* d_in, const int* in_sizes, int n_in,
                              void* d_out, int out_size)
{
    const float* em     = (const float*)d_in[0];
    const void*  tags   = (const void*)d_in[1];
    const int*   mask   = (const int*)d_in[2];
    const float* startT = (const float*)d_in[3];
    const float* endT   = (const float*)d_in[4];
    const float* trans  = (const float*)d_in[5];
    float* out = (float*)d_out;

    crf_kernel<<<2 * BATCH, TPB>>>(em, tags, mask, startT, endT, trans, out);
}